// round 4
// baseline (speedup 1.0000x reference)
#include <cuda_runtime.h>
#include <cuda_bf16.h>
#include <cstdint>

// Backlash scan, B=4096, T=2048. Single fused kernel, exact result:
//  - 16 chunks/sequence, 24-step speculative warm-up
//  - depth-2 cp.async pipeline (3 buffers, 4 steps/stage, 38 stages)
//  - smem output accumulator, 64B-coalesced flushes overlapped with waits
//  - in-block chunk-boundary validation + serial replay backstop

#define BB 4096
#define TT 2048
#define CHUNKS 16
#define LCH 128
#define SS 4
#define WARMS 6
#define WARM (WARMS * SS)      // 24
#define NEMIT (LCH / SS)       // 32
#define NST (WARMS + NEMIT)    // 38
#define TPB 128
#define STR 5                  // float4 per stream per stage buffer: 4 w + 1 x
#define OROW 28                // floats per stream in sOut (16 data + 12 pad)
#define NBUF 3

// One backlash step, bit-identical to the reference fp32 expression.
// h-thresholds via sign tests (exact for nonzero m).
__device__ __forceinline__ float bl_step(float prev, float xt, float4 wv) {
    float m_lo = wv.x, m_up = wv.y, c_lo = wv.z, c_up = wv.w;
    float a  = __fmul_rn(m_lo, xt);
    float bq = __fmul_rn(m_lo, c_lo);
    float cc = __fmul_rn(m_up, xt);
    float d  = __fmul_rn(m_up, c_up);
    float A1 = __fsub_rn(__fadd_rn(a, bq), prev);
    float A2 = __fsub_rn(__fsub_rn(prev, cc), d);
    bool p1 = ((A1 > 0.0f) && (m_lo > 0.0f)) || ((A1 < 0.0f) && (m_lo < 0.0f));
    bool p2 = ((A2 > 0.0f) && (m_up > 0.0f)) || ((A2 < 0.0f) && (m_up < 0.0f));
    float t1 = p1 ? 0.0f : a;
    float t2 = p1 ? 0.0f : bq;
    float t3 = p2 ? 0.0f : cc;
    float t4 = p2 ? 0.0f : d;
    float t5 = (p1 && p2) ? prev : 0.0f;
    return __fadd_rn(__fadd_rn(__fadd_rn(__fadd_rn(t1, t2), t3), t4), t5);
}

__device__ __forceinline__ void cp16(uint32_t dst, const float4* src) {
    asm volatile("cp.async.cg.shared.global [%0], [%1], 16;" :: "r"(dst), "l"(src));
}

// Coalesced cp.async copies for stage s (10 KB: w 16B/step, x 4B/step).
__device__ __forceinline__ void issue_stage(const float* __restrict__ x,
                                            const float* __restrict__ w,
                                            int b_blk, int s, uint32_t sb32, int tid) {
    #pragma unroll
    for (int it = 0; it < 4; it++) {
        int sidx = it * 32 + (tid >> 2);      // block-local stream
        int j    = tid & 3;
        int sc   = sidx & 15;
        int sb   = b_blk + (sidx >> 4);
        int tb   = sc * LCH - WARM + s * SS;
        if (tb < 0) tb = 0;                   // c==0 warm clamp (discarded)
        cp16(sb32 + (uint32_t)(sidx * STR + j) * 16,
             (const float4*)w + (size_t)sb * TT + tb + j);
    }
    {
        int sc = tid & 15;
        int sb = b_blk + (tid >> 4);
        int tb = sc * LCH - WARM + s * SS;
        if (tb < 0) tb = 0;
        cp16(sb32 + (uint32_t)(tid * STR + 4) * 16,
             (const float4*)(x + (size_t)sb * TT + tb));
    }
    asm volatile("cp.async.commit_group;");
}

// Flush one 16-step window: 128 streams x 64B, coalesced float4 stores.
__device__ __forceinline__ void flush_win(float* __restrict__ out, const float* sO,
                                          int b_blk, int win, int tid) {
    #pragma unroll
    for (int it = 0; it < 4; it++) {
        int fidx   = it * 128 + tid;
        int stream = fidx >> 2;
        int q      = fidx & 3;
        int sb     = b_blk + (stream >> 4);
        int sc     = stream & 15;
        float4 v = *(const float4*)(sO + stream * OROW + q * 4);
        ((float4*)out)[(size_t)sb * (TT / 4) + sc * (LCH / 4) + win * 4 + q] = v;
    }
}

__global__ __launch_bounds__(TPB)
void backlash_fused(const float* __restrict__ x,
                    const float* __restrict__ w,
                    const float* __restrict__ out_prev,
                    float* __restrict__ out) {
    __shared__ float4 sIn[NBUF][TPB * STR];   // 30720 B
    __shared__ float  sO[TPB * OROW];         // 14336 B
    __shared__ float  sG[TPB], sE[TPB];

    const int tid   = threadIdx.x;
    const int b_blk = blockIdx.x * 8;         // 8 sequences per block
    const int my_c  = tid & 15;
    const int my_b  = b_blk + (tid >> 4);

    uint32_t sb32[NBUF];
    #pragma unroll
    for (int i = 0; i < NBUF; i++)
        sb32[i] = (uint32_t)__cvta_generic_to_shared(&sIn[i][0]);

    // Prefetch initial state (consumed at stage WARMS-1).
    float op = (my_c == 0) ? out_prev[my_b] : 0.0f;
    float prev = 0.0f;

    issue_stage(x, w, b_blk, 0, sb32[0], tid);
    issue_stage(x, w, b_blk, 1, sb32[1], tid);

    for (int s = 0; s < NST; s++) {
        if (s + 2 < NST)
            issue_stage(x, w, b_blk, s + 2, sb32[(s + 2) % NBUF], tid);

        // Flush previous window while this stage's data is still in flight.
        int ep = s - 1 - WARMS;
        if (ep >= 0 && (ep & 3) == 3)
            flush_win(out, sO, b_blk, ep >> 2, tid);

        int pn = NST - 1 - s;
        if (pn >= 2)      { asm volatile("cp.async.wait_group 2;"); }
        else if (pn == 1) { asm volatile("cp.async.wait_group 1;"); }
        else              { asm volatile("cp.async.wait_group 0;"); }
        __syncthreads();

        const float4* bp = &sIn[s % NBUF][tid * STR];
        float4 x4 = bp[4];
        float o0, o1, o2, o3;
        prev = bl_step(prev, x4.x, bp[0]); o0 = prev;
        prev = bl_step(prev, x4.y, bp[1]); o1 = prev;
        prev = bl_step(prev, x4.z, bp[2]); o2 = prev;
        prev = bl_step(prev, x4.w, bp[3]); o3 = prev;

        int e = s - WARMS;
        if (e >= 0)
            *(float4*)(sO + tid * OROW + (e & 3) * 4) = make_float4(o0, o1, o2, o3);
        if (s == WARMS - 1) {             // warm-up complete
            if (my_c == 0) prev = op;
            sG[tid] = prev;
        }
        __syncthreads();
    }
    flush_win(out, sO, b_blk, 7, tid);    // last window

    // ---- in-block validation + replay backstop (exactness guarantee) ----
    sE[tid] = prev;
    __syncthreads();

    if (tid < 8) {
        const int b = b_blk + tid;
        const float*  xb = x + (size_t)b * TT;
        const float4* wb = (const float4*)w + (size_t)b * TT;
        float*        ob = out + (size_t)b * TT;
        float st = sE[tid * 16];
        #pragma unroll 1
        for (int c = 1; c < CHUNKS; c++) {
            if (st == sG[tid * 16 + c]) {
                st = sE[tid * 16 + c];
            } else {
                // speculative warm-up failed to merge: serial replay of chunk c
                for (int t = c * LCH; t < (c + 1) * LCH; t++) {
                    st = bl_step(st, xb[t], wb[t]);
                    ob[t] = st;
                }
            }
        }
    }
}

extern "C" void kernel_launch(void* const* d_in, const int* in_sizes, int n_in,
                              void* d_out, int out_size) {
    const float* x = nullptr;        // (B, T, 1)
    const float* out_prev = nullptr; // (B, 1, 1)
    const float* w = nullptr;        // (B, T, 4)
    for (int i = 0; i < n_in; i++) {
        if (in_sizes[i] == BB * TT)          x = (const float*)d_in[i];
        else if (in_sizes[i] == BB)          out_prev = (const float*)d_in[i];
        else if (in_sizes[i] == BB * TT * 4) w = (const float*)d_in[i];
    }
    float* out = (float*)d_out;

    backlash_fused<<<BB / 8, TPB>>>(x, w, out_prev, out);
}

// round 5
// speedup vs baseline: 1.3744x; 1.3744x over previous
#include <cuda_runtime.h>
#include <cuda_bf16.h>
#include <cstdint>

// Backlash scan, B=4096, T=2048. Single fused kernel, exact result:
//  - 16 chunks/sequence, 24-step speculative warm-up
//  - SS=8 steps/stage, 19 stages, triple-buffered cp.async (issue 2 ahead)
//  - in-block chunk-boundary validation + serial replay backstop

#define BB 4096
#define TT 2048
#define CHUNKS 16
#define LCH 128
#define SS 8
#define WARMS 3
#define WARM (WARMS * SS)       // 24
#define NST (WARMS + LCH / SS)  // 19
#define TPB 128
#define STR 11                  // float4/stream/stage: 8 w + 2 x + 1 pad
#define NBUF 3

// One backlash step, bit-identical to the reference fp32 expression.
// h-thresholds via sign tests (exact for nonzero m).
__device__ __forceinline__ float bl_step(float prev, float xt, float4 wv) {
    float m_lo = wv.x, m_up = wv.y, c_lo = wv.z, c_up = wv.w;
    float a  = __fmul_rn(m_lo, xt);
    float bq = __fmul_rn(m_lo, c_lo);
    float cc = __fmul_rn(m_up, xt);
    float d  = __fmul_rn(m_up, c_up);
    float A1 = __fsub_rn(__fadd_rn(a, bq), prev);
    float A2 = __fsub_rn(__fsub_rn(prev, cc), d);
    bool p1 = ((A1 > 0.0f) && (m_lo > 0.0f)) || ((A1 < 0.0f) && (m_lo < 0.0f));
    bool p2 = ((A2 > 0.0f) && (m_up > 0.0f)) || ((A2 < 0.0f) && (m_up < 0.0f));
    float t1 = p1 ? 0.0f : a;
    float t2 = p1 ? 0.0f : bq;
    float t3 = p2 ? 0.0f : cc;
    float t4 = p2 ? 0.0f : d;
    float t5 = (p1 && p2) ? prev : 0.0f;
    return __fadd_rn(__fadd_rn(__fadd_rn(__fadd_rn(t1, t2), t3), t4), t5);
}

__device__ __forceinline__ void cp16(uint32_t dst, const float4* src) {
    asm volatile("cp.async.cg.shared.global [%0], [%1], 16;" :: "r"(dst), "l"(src));
}

// Coalesced cp.async copies for stage s (22.5 KB: w 16B/step, x 4B/step).
__device__ __forceinline__ void issue_stage(const float* __restrict__ x,
                                            const float* __restrict__ w,
                                            int b_blk, int s, uint32_t sb32, int tid) {
    // w: 128 streams x 8 float4 (8 per thread; 8 lanes cover 128B per stream)
    #pragma unroll
    for (int it = 0; it < 8; it++) {
        int sidx  = it * 16 + (tid >> 3);
        int j     = tid & 7;
        int sb    = b_blk + (sidx >> 4);
        int sc    = sidx & 15;
        int tbase = sc * LCH - WARM + s * SS;
        if (tbase < 0) tbase = 0;              // c==0 warm clamp (discarded)
        cp16(sb32 + (uint32_t)(sidx * STR + j) * 16,
             (const float4*)w + (size_t)sb * TT + tbase + j);
    }
    // x: 128 streams x 2 float4 (2 per thread)
    #pragma unroll
    for (int it = 0; it < 2; it++) {
        int sidx  = it * 64 + (tid >> 1);
        int k     = tid & 1;
        int sb    = b_blk + (sidx >> 4);
        int sc    = sidx & 15;
        int tbase = sc * LCH - WARM + s * SS;
        if (tbase < 0) tbase = 0;
        cp16(sb32 + (uint32_t)(sidx * STR + 8 + k) * 16,
             (const float4*)(x + (size_t)sb * TT + tbase) + k);
    }
    asm volatile("cp.async.commit_group;");
}

__global__ __launch_bounds__(TPB)
void backlash_fused(const float* __restrict__ x,
                    const float* __restrict__ w,
                    const float* __restrict__ out_prev,
                    float* __restrict__ out) {
    __shared__ float4 sB[NBUF][TPB * STR];   // 67584 B
    __shared__ float  sG[TPB];               // state entering chunk (post warm-up)
    __shared__ float  sE[TPB];               // state leaving chunk

    const int tid   = threadIdx.x;
    const int b_blk = blockIdx.x * 8;        // 8 sequences per block
    const int my_c  = tid & 15;
    const int my_b  = b_blk + (tid >> 4);

    const uint32_t a0 = (uint32_t)__cvta_generic_to_shared(&sB[0][0]);
    const uint32_t a1 = (uint32_t)__cvta_generic_to_shared(&sB[1][0]);
    const uint32_t a2 = (uint32_t)__cvta_generic_to_shared(&sB[2][0]);

    // Prefetch initial state (consumed at stage WARMS-1).
    float op = (my_c == 0) ? out_prev[my_b] : 0.0f;
    float prev = 0.0f;

    issue_stage(x, w, b_blk, 0, a0, tid);
    issue_stage(x, w, b_blk, 1, a1, tid);

    for (int s = 0; s < NST; s++) {
        const int m = s % NBUF;
        if (s + 2 < NST) {
            const int mn = (s + 2) % NBUF;
            issue_stage(x, w, b_blk, s + 2, mn == 0 ? a0 : (mn == 1 ? a1 : a2), tid);
        }
        // Groups complete in order; require group s done.
        int slack = (s + 2 < NST) ? 2 : (s + 1 < NST ? 1 : 0);
        if (slack == 2)      { asm volatile("cp.async.wait_group 2;"); }
        else if (slack == 1) { asm volatile("cp.async.wait_group 1;"); }
        else                 { asm volatile("cp.async.wait_group 0;"); }
        __syncthreads();

        const bool emit = (s >= WARMS);
        if (emit || my_c > 0) {
            float4 x0 = sB[m][tid * STR + 8];
            float4 x1 = sB[m][tid * STR + 9];
            float xv[8] = {x0.x, x0.y, x0.z, x0.w, x1.x, x1.y, x1.z, x1.w};
            float o[8];
            #pragma unroll
            for (int j = 0; j < SS; j++) {
                float4 wv = sB[m][tid * STR + j];
                prev = bl_step(prev, xv[j], wv);
                o[j] = prev;
            }
            if (emit) {
                // outputs back into the (consumed) x slots, conflict-free STS.128
                sB[m][tid * STR + 8] = make_float4(o[0], o[1], o[2], o[3]);
                sB[m][tid * STR + 9] = make_float4(o[4], o[5], o[6], o[7]);
            }
        }
        if (s == WARMS - 1) {            // warm-up complete
            if (my_c == 0) prev = op;
            sG[tid] = prev;
        }
        __syncthreads();

        if (emit) {
            // coalesced float4 write of this stage's outputs
            #pragma unroll
            for (int it = 0; it < 2; it++) {
                int sidx = it * 64 + (tid >> 1);
                int k    = tid & 1;
                int sb   = b_blk + (sidx >> 4);
                int sc   = sidx & 15;
                float4 v = sB[m][sidx * STR + 8 + k];
                ((float4*)out)[(size_t)sb * (TT / 4) + sc * (LCH / 4)
                               + (s - WARMS) * (SS / 4) + k] = v;
            }
            __syncthreads();   // outputs consumed before this buffer is refilled
        }
    }

    // ---- in-block validation + replay backstop (exactness guarantee) ----
    sE[tid] = prev;
    __syncthreads();

    if (tid < 8) {
        const int b = b_blk + tid;
        const float*  xb = x + (size_t)b * TT;
        const float4* wb = (const float4*)w + (size_t)b * TT;
        float*        ob = out + (size_t)b * TT;
        float st = sE[tid * 16];
        #pragma unroll 1
        for (int c = 1; c < CHUNKS; c++) {
            if (st == sG[tid * 16 + c]) {
                st = sE[tid * 16 + c];
            } else {
                // speculative warm-up failed to merge: serial replay of chunk c
                for (int t = c * LCH; t < (c + 1) * LCH; t++) {
                    st = bl_step(st, xb[t], wb[t]);
                    ob[t] = st;
                }
            }
        }
    }
}

extern "C" void kernel_launch(void* const* d_in, const int* in_sizes, int n_in,
                              void* d_out, int out_size) {
    const float* x = nullptr;        // (B, T, 1)
    const float* out_prev = nullptr; // (B, 1, 1)
    const float* w = nullptr;        // (B, T, 4)
    for (int i = 0; i < n_in; i++) {
        if (in_sizes[i] == BB * TT)          x = (const float*)d_in[i];
        else if (in_sizes[i] == BB)          out_prev = (const float*)d_in[i];
        else if (in_sizes[i] == BB * TT * 4) w = (const float*)d_in[i];
    }
    float* out = (float*)d_out;

    backlash_fused<<<BB / 8, TPB>>>(x, w, out_prev, out);
}

// round 7
// speedup vs baseline: 1.6959x; 1.2339x over previous
#include <cuda_runtime.h>
#include <cuda_bf16.h>
#include <cstdint>

// Backlash scan, B=4096, T=2048. Warp-autonomous fused kernel, exact result:
//  - each warp owns 2 sequences (32 streams = 2 seq x 16 chunks), runs its own
//    double-buffered cp.async pipeline; NO __syncthreads anywhere
//  - 24-step speculative warm-up, 8 steps/stage, 19 stages
//  - warp-local shfl validation + serial replay backstop

#define BB 4096
#define TT 2048
#define CHUNKS 16
#define LCH 128
#define SS 8
#define WARMS 3
#define WARM (WARMS * SS)       // 24
#define NST (WARMS + LCH / SS)  // 19
#define TPB 128
#define NW (TPB / 32)
#define STR 11                  // float4/stream/stage: 8 w + 2 x + 1 pad
#define NBUF 2

// One backlash step, bit-identical to the reference fp32 expression.
// h-thresholds via sign tests (exact for nonzero m).
__device__ __forceinline__ float bl_step(float prev, float xt, float4 wv) {
    float m_lo = wv.x, m_up = wv.y, c_lo = wv.z, c_up = wv.w;
    float a  = __fmul_rn(m_lo, xt);
    float bq = __fmul_rn(m_lo, c_lo);
    float cc = __fmul_rn(m_up, xt);
    float d  = __fmul_rn(m_up, c_up);
    float A1 = __fsub_rn(__fadd_rn(a, bq), prev);
    float A2 = __fsub_rn(__fsub_rn(prev, cc), d);
    bool p1 = ((A1 > 0.0f) && (m_lo > 0.0f)) || ((A1 < 0.0f) && (m_lo < 0.0f));
    bool p2 = ((A2 > 0.0f) && (m_up > 0.0f)) || ((A2 < 0.0f) && (m_up < 0.0f));
    float t1 = p1 ? 0.0f : a;
    float t2 = p1 ? 0.0f : bq;
    float t3 = p2 ? 0.0f : cc;
    float t4 = p2 ? 0.0f : d;
    float t5 = (p1 && p2) ? prev : 0.0f;
    return __fadd_rn(__fadd_rn(__fadd_rn(__fadd_rn(t1, t2), t3), t4), t5);
}

__device__ __forceinline__ void cp16(uint32_t dst, const float4* src) {
    asm volatile("cp.async.cg.shared.global [%0], [%1], 16;" :: "r"(dst), "l"(src));
}

// Warp-scope coalesced cp.async copies for stage s (5 KB: 32 streams).
__device__ __forceinline__ void issue_stage_w(const float* __restrict__ x,
                                              const float* __restrict__ w,
                                              int seq0, int s, uint32_t sb32, int lane) {
    // w: 8 passes x (4 streams x 8 lanes -> 4 full 128B segments / instr)
    #pragma unroll
    for (int p = 0; p < 8; p++) {
        int st = p * 4 + (lane >> 3);
        int j  = lane & 7;
        int sb = seq0 + (st >> 4);
        int sc = st & 15;
        int tb = sc * LCH - WARM + s * SS;
        if (tb < 0) tb = 0;                 // c==0 warm clamp (discarded)
        cp16(sb32 + (uint32_t)(st * STR + j) * 16,
             (const float4*)w + (size_t)sb * TT + tb + j);
    }
    // x: 2 passes x (16 streams x lane-pairs -> full 32B sectors)
    #pragma unroll
    for (int p = 0; p < 2; p++) {
        int st = p * 16 + (lane >> 1);
        int k  = lane & 1;
        int sb = seq0 + (st >> 4);
        int sc = st & 15;
        int tb = sc * LCH - WARM + s * SS;
        if (tb < 0) tb = 0;
        cp16(sb32 + (uint32_t)(st * STR + 8 + k) * 16,
             (const float4*)(x + (size_t)sb * TT + tb) + k);
    }
    asm volatile("cp.async.commit_group;");
}

__global__ __launch_bounds__(TPB)
void backlash_fused(const float* __restrict__ x,
                    const float* __restrict__ w,
                    const float* __restrict__ out_prev,
                    float* __restrict__ out) {
    __shared__ float4 sB[NW][NBUF][32 * STR];   // 45056 B

    const int tid  = threadIdx.x;
    const int lane = tid & 31;
    const int wrp  = tid >> 5;
    const int seq0 = blockIdx.x * (2 * NW) + wrp * 2;   // 2 sequences per warp
    const int my_b = seq0 + (lane >> 4);
    const int my_c = lane & 15;

    const uint32_t b0 = (uint32_t)__cvta_generic_to_shared(&sB[wrp][0][0]);
    const uint32_t b1 = (uint32_t)__cvta_generic_to_shared(&sB[wrp][1][0]);

    const float op = (my_c == 0) ? out_prev[my_b] : 0.0f;
    float prev = 0.0f;
    float G = 0.0f;                 // state entering my chunk (post warm-up)

    issue_stage_w(x, w, seq0, 0, b0, lane);
    issue_stage_w(x, w, seq0, 1, b1, lane);

    #pragma unroll 1
    for (int s = 0; s < NST; s++) {
        if (s == NST - 1) { asm volatile("cp.async.wait_group 0;"); }
        else              { asm volatile("cp.async.wait_group 1;"); }
        __syncwarp();

        const uint32_t cb = (s & 1) ? b1 : b0;
        const float4* bp = &sB[wrp][s & 1][lane * STR];
        float4 x0 = bp[8];
        float4 x1 = bp[9];
        float o0, o1, o2, o3, o4, o5, o6, o7;
        prev = bl_step(prev, x0.x, bp[0]); o0 = prev;
        prev = bl_step(prev, x0.y, bp[1]); o1 = prev;
        prev = bl_step(prev, x0.z, bp[2]); o2 = prev;
        prev = bl_step(prev, x0.w, bp[3]); o3 = prev;
        prev = bl_step(prev, x1.x, bp[4]); o4 = prev;
        prev = bl_step(prev, x1.y, bp[5]); o5 = prev;
        prev = bl_step(prev, x1.z, bp[6]); o6 = prev;
        prev = bl_step(prev, x1.w, bp[7]); o7 = prev;

        const bool emit = (s >= WARMS);
        if (emit) {
            // outputs into the consumed x slots (conflict-free STS.128)
            float4* wp = &sB[wrp][s & 1][lane * STR];
            wp[8] = make_float4(o0, o1, o2, o3);
            wp[9] = make_float4(o4, o5, o6, o7);
        }
        if (s == WARMS - 1) {               // warm-up complete
            if (my_c == 0) prev = op;
            G = prev;
        }
        __syncwarp();

        if (emit) {
            // coalesced float4 stores (lane pairs; full 32B sectors)
            #pragma unroll
            for (int p = 0; p < 2; p++) {
                int st = p * 16 + (lane >> 1);
                int k  = lane & 1;
                int sb = seq0 + (st >> 4);
                int sc = st & 15;
                float4 v = sB[wrp][s & 1][st * STR + 8 + k];
                ((float4*)out)[(size_t)sb * (TT / 4) + sc * (LCH / 4)
                               + (s - WARMS) * (SS / 4) + k] = v;
            }
        }
        if (s + 2 < NST)
            issue_stage_w(x, w, seq0, s + 2, cb, lane);   // (s+2)&1 == s&1
    }

    // ---- warp-local validation + replay backstop (exactness guarantee) ----
    const unsigned full = 0xFFFFFFFFu;
    float E = prev;
    float Ep = __shfl_up_sync(full, E, 1);
    bool ok = (my_c == 0) || (Ep == G);
    if (__ballot_sync(full, ok) != full) {
        // Rare: speculative warm-up failed to merge somewhere in this warp.
        int base = lane & 16;
        float st = E;                       // valid on owner lanes (my_c==0)
        #pragma unroll 1
        for (int c = 1; c < CHUNKS; c++) {
            float g = __shfl_sync(full, G, base + c);
            float e = __shfl_sync(full, E, base + c);
            if (my_c == 0) {
                if (st == g) {
                    st = e;
                } else {
                    const float*  xb = x + (size_t)my_b * TT;
                    const float4* wb = (const float4*)w + (size_t)my_b * TT;
                    float*        ob = out + (size_t)my_b * TT;
                    for (int t = c * LCH; t < (c + 1) * LCH; t++) {
                        st = bl_step(st, xb[t], wb[t]);
                        ob[t] = st;
                    }
                }
            }
        }
    }
}

extern "C" void kernel_launch(void* const* d_in, const int* in_sizes, int n_in,
                              void* d_out, int out_size) {
    const float* x = nullptr;        // (B, T, 1)
    const float* out_prev = nullptr; // (B, 1, 1)
    const float* w = nullptr;        // (B, T, 4)
    for (int i = 0; i < n_in; i++) {
        if (in_sizes[i] == BB * TT)          x = (const float*)d_in[i];
        else if (in_sizes[i] == BB)          out_prev = (const float*)d_in[i];
        else if (in_sizes[i] == BB * TT * 4) w = (const float*)d_in[i];
    }
    float* out = (float*)d_out;

    backlash_fused<<<BB / (2 * NW), TPB>>>(x, w, out_prev, out);
}